// round 10
// baseline (speedup 1.0000x reference)
#include <cuda_runtime.h>
#include <math.h>

#define NMOL 256
#define NPER 32
#define NNODE 8192
#define EPM 992
#define ETOT (NMOL*EPM)
#define SD 256
#define ED 32
#define MSG_IN 546
#define MSG_OUT 353
#define NT 512
#define HROWS 16

typedef unsigned long long u64;

// global scratch (sanctioned __device__ arrays)
__device__ float g_e[(size_t)ETOT*ED];                  // edge features (32.5MB)
__device__ float g_hdn[(size_t)ETOT*SD];                // per-layer hidden acts (260MB)
__device__ __align__(16) float g_w2t[5*64*32*4];        // transposed W2e [l][c4][k][4]
__device__ __align__(16) float g_Q  [(size_t)NMOL*NPER*SD];
__device__ __align__(16) float g_S0 [(size_t)NMOL*NPER*SD];
__device__ __align__(16) float g_s  [(size_t)NMOL*NPER*SD];
__device__ float g_pos[NMOL*NPER*3];

__device__ __forceinline__ float silu_f(float v){
    return v * (1.0f / (1.0f + __expf(-v)));
}
__device__ __forceinline__ u64 pack2(float x, float y){
    u64 r; asm("mov.b64 %0, {%1, %2};" : "=l"(r) : "f"(x), "f"(y)); return r;
}
__device__ __forceinline__ void unpack2(u64 v, float& x, float& y){
    asm("mov.b64 {%0, %1}, %2;" : "=f"(x), "=f"(y) : "l"(v));
}
__device__ __forceinline__ u64 fma2(u64 a, u64 b, u64 c){
    u64 d; asm("fma.rn.f32x2 %0, %1, %2, %3;" : "=l"(d) : "l"(a), "l"(b), "l"(c)); return d;
}
__device__ __forceinline__ u64 add2(u64 a, u64 b){
    u64 d; asm("add.rn.f32x2 %0, %1, %2;" : "=l"(d) : "l"(a), "l"(b)); return d;
}
__device__ __forceinline__ u64 dup2(float x){ return pack2(x,x); }

// ---------------- prep: transpose W2e ----------------
__global__ void prep_kernel(const float* __restrict__ gW2){
    int idx = blockIdx.x*256 + threadIdx.x;
    if (idx >= 5*8192) return;
    int l = idx >> 13; int rem = idx & 8191;
    int c4 = rem >> 7; int rem2 = rem & 127;
    int k = rem2 >> 2; int cc = rem2 & 3;
    g_w2t[idx] = gW2[((size_t)l*256 + 4*c4 + cc)*MSG_OUT + 321 + k];
}

// ---------------- K0: embed + e init ----------------
__global__ void __launch_bounds__(NT,2) k0_kernel(
    const float* __restrict__ x,   const float* __restrict__ z,
    const float* __restrict__ rot, const float* __restrict__ eattr,
    const float* __restrict__ Wam, const float* __restrict__ bam,
    const float* __restrict__ Wbm, const float* __restrict__ bbm)
{
    __shared__ float xz[NPER*80];
    __shared__ float tmp[NPER*3];
    const int tid = threadIdx.x;
    const int mol = blockIdx.x;
    const int nodeBase = mol * NPER;
    const size_t ebase = (size_t)mol * EPM;
    const int c  = tid & 255;
    const int r0 = (tid >> 8) * HROWS;
    float* sg = g_s + (size_t)mol*NPER*SD;

    for (int idx = tid; idx < NPER*80; idx += NT){
        int i = idx / 80, k = idx % 80;
        xz[idx] = (k < 16) ? x[(nodeBase+i)*16 + k] : z[(nodeBase+i)*64 + (k-16)];
    }
    __syncthreads();
    {
        float acc[HROWS];
#pragma unroll
        for (int r=0;r<HROWS;r++) acc[r]=0.f;
        for (int kg=0; kg<20; kg++){
            float w0=Wam[(4*kg+0)*259+c], w1=Wam[(4*kg+1)*259+c];
            float w2v=Wam[(4*kg+2)*259+c], w3=Wam[(4*kg+3)*259+c];
#pragma unroll
            for (int r=0;r<HROWS;r++){
                float4 v = ((const float4*)xz)[(r0+r)*20+kg];
                acc[r] += v.x*w0 + v.y*w1 + v.z*w2v + v.w*w3;
            }
        }
        float b = bam[c];
#pragma unroll
        for (int r=0;r<HROWS;r++) sg[(r0+r)*SD + c] = acc[r] + b;
    }
    if (tid < 96){
        int i = tid/3, cc = tid%3;
        float a = bam[256+cc];
        for (int k=0;k<80;k++) a += xz[i*80+k]*Wam[k*259+256+cc];
        tmp[i*3+cc] = a;
    }
    __syncthreads();
    if (tid < 96){
        int i = tid/3, cc = tid%3;
        float pv = 0.f;
#pragma unroll
        for (int q=0;q<3;q++) pv += rot[mol*9 + cc*3 + q]*tmp[i*3+q];
        g_pos[mol*96 + i*3 + cc] = pv;
    }
    for (int idx = tid; idx < EPM*ED; idx += NT){
        int eL = idx >> 5, k = idx & 31;
        const float* ea = &eattr[(ebase+eL)*5];
        float a = bbm[k];
#pragma unroll
        for (int q=0;q<5;q++) a += ea[q]*Wbm[q*ED+k];
        g_e[(ebase+eL)*ED + k] = a;
    }
}

// ---------------- K1: per-layer message pass (no e-update) ----------------
struct SM1 {
    float P   [NPER][SD];   // 32KB
    float hdn [NPER][SD];   // 32KB (for C1/S0)
    float W1c [ED][SD];     // 32KB
    float esm2[NPER][2*ED]; // 8KB
    float s0q [4][SD];      // 4KB
    float w2p [SD];
    float pos [NPER][3];
    float npos[NPER][3];
    float dbuf[NPER];
    float abuf[NPER];
    float rnb [NPER][3];
    float pdpart[16][3];
};

__global__ void __launch_bounds__(NT,2) k1_kernel(
    const float* __restrict__ gW1, const float* __restrict__ gb1,
    const float* __restrict__ gW2, const float* __restrict__ gb2,
    int l)
{
    extern __shared__ float smraw[];
    SM1* sm = (SM1*)smraw;
    const int tid  = threadIdx.x;
    const int lane = tid & 31;
    const int wrp  = tid >> 5;
    const int mol  = blockIdx.x;
    const size_t ebase = (size_t)mol * EPM;
    const int c  = tid & 255;
    const int r0 = (tid >> 8) * HROWS;
    const int p  = tid & 127;
    const int q4 = tid >> 7;
    const int rq = q4 * 8;
    float* Qg  = g_Q  + (size_t)mol*NPER*SD;
    float* S0g = g_S0 + (size_t)mol*NPER*SD;
    float* sg  = g_s  + (size_t)mol*NPER*SD;

    const float* W1 = gW1 + (size_t)l*MSG_IN*SD;
    const float* b1 = gb1 + l*SD;
    const float* W2 = gW2 + (size_t)l*SD*MSG_OUT;
    const float* b2 = gb2 + l*MSG_OUT;

    if (tid < 96) sm->pos[tid/3][tid%3] = g_pos[mol*96 + tid];
    for (int idx = tid; idx < ED*SD; idx += NT)
        sm->W1c[idx>>8][idx&255] = W1[512*SD + idx];
    if (tid < 256) sm->w2p[tid] = W2[tid*MSG_OUT + 320];
    if (tid < 96) sm->npos[tid/3][tid%3] = 0.f;

    // P = s@W1a -> SMEM
    {
        float acc[HROWS];
#pragma unroll
        for (int r=0;r<HROWS;r++) acc[r]=0.f;
        for (int kg=0; kg<64; kg++){
            float wa0=W1[(4*kg+0)*SD+c], wa1=W1[(4*kg+1)*SD+c];
            float wa2=W1[(4*kg+2)*SD+c], wa3=W1[(4*kg+3)*SD+c];
#pragma unroll
            for (int r=0;r<HROWS;r++){
                const float4 v = __ldg((const float4*)&sg[(r0+r)*SD + 4*kg]);
                acc[r] += v.x*wa0 + v.y*wa1 + v.z*wa2 + v.w*wa3;
            }
        }
#pragma unroll
        for (int r=0;r<HROWS;r++) sm->P[r0+r][c]=acc[r];
    }
    // Q = s@W1b + b1 -> global
    {
        float acc[HROWS];
#pragma unroll
        for (int r=0;r<HROWS;r++) acc[r]=0.f;
        for (int kg=0; kg<64; kg++){
            float wb0=W1[(256+4*kg+0)*SD+c], wb1=W1[(256+4*kg+1)*SD+c];
            float wb2=W1[(256+4*kg+2)*SD+c], wb3=W1[(256+4*kg+3)*SD+c];
#pragma unroll
            for (int r=0;r<HROWS;r++){
                const float4 v = __ldg((const float4*)&sg[(r0+r)*SD + 4*kg]);
                acc[r] += v.x*wb0 + v.y*wb1 + v.z*wb2 + v.w*wb3;
            }
        }
        float bb = b1[c];
#pragma unroll
        for (int r=0;r<HROWS;r++) Qg[(r0+r)*SD + c] = acc[r]+bb;
    }
    __syncthreads();

    const u64 w1d2 = __ldg((const u64*)&W1[544*SD + 2*p]);
    const u64 w1e2 = __ldg((const u64*)&W1[545*SD + 2*p]);
    const float b2p = __ldg(&b2[320]);

    for (int j=0; j<NPER; j++){
        // [A] fold prev pdpart; stage e rows (dup) + geometry
        if (j>0 && tid<3){
            float sum=0.f;
#pragma unroll
            for (int w=0;w<16;w++) sum += sm->pdpart[w][tid];
            sm->npos[j-1][tid] += sum;
        }
        for (int idx = tid; idx < NPER*ED; idx += NT){
            int i = idx>>5, k = idx&31;
            float v = 0.f;
            if (i != j){
                int eL = i*31 + j - (j>i);
                v = g_e[(ebase+eL)*ED + k];
            }
            *(float2*)&sm->esm2[i][2*k] = make_float2(v, v);
        }
        if (tid < NPER){
            int i = tid;
            float pix=sm->pos[i][0], piy=sm->pos[i][1], piz=sm->pos[i][2];
            float pjx=sm->pos[j][0], pjy=sm->pos[j][1], pjz=sm->pos[j][2];
            float rx=pjx-pix, ry=pjy-piy, rz=pjz-piz;
            float d = sqrtf(fmaxf(rx*rx+ry*ry+rz*rz, 1e-6f));
            float inv = 1.f/(1.f+d);
            sm->dbuf[i]=d; sm->abuf[i]=pix*pjx+piy*pjy+piz*pjz;
            if (i==j){rx=0;ry=0;rz=0;}
            sm->rnb[i][0]=rx*inv; sm->rnb[i][1]=ry*inv; sm->rnb[i][2]=rz*inv;
        }
        __syncthreads();

        // [B] hdn = silu(P+Q+e@W1c+d*w1d+a*w1e); write SMEM + g_hdn
        {
            u64 acc[8];
            const u64 Q2 = __ldg((const u64*)&Qg[j*SD + 2*p]);
#pragma unroll
            for (int r=0;r<8;r++){
                int i = rq + r;
                u64 t = add2(*(const u64*)&sm->P[i][2*p], Q2);
                t = fma2(dup2(sm->dbuf[i]), w1d2, t);
                t = fma2(dup2(sm->abuf[i]), w1e2, t);
                acc[r] = t;
            }
#pragma unroll 4
            for (int k2=0;k2<16;k2++){
                u64 w0 = *(const u64*)&sm->W1c[2*k2  ][2*p];
                u64 w1 = *(const u64*)&sm->W1c[2*k2+1][2*p];
#pragma unroll
                for (int r=0;r<8;r++){
                    const ulonglong2 e2 = *(const ulonglong2*)&sm->esm2[rq+r][4*k2];
                    acc[r] = fma2(e2.x, w0, acc[r]);
                    acc[r] = fma2(e2.y, w1, acc[r]);
                }
            }
            float s0x=0.f, s0y=0.f;
#pragma unroll
            for (int r=0;r<8;r++){
                int i = rq + r;
                float hx,hy; unpack2(acc[r],hx,hy);
                hx = silu_f(hx); hy = silu_f(hy);
                if (i==j){ hx=0.f; hy=0.f; }
                *(float2*)&sm->hdn[i][2*p] = make_float2(hx,hy);
                if (i != j){
                    int eL = i*31 + j - (j>i);
                    *(float2*)&g_hdn[((size_t)(ebase+eL))*SD + 2*p] = make_float2(hx,hy);
                }
                s0x += hx; s0y += hy;
            }
            *(float2*)&sm->s0q[q4][2*p] = make_float2(s0x,s0y);
        }
        __syncthreads();

        // [C0] S0 row j
        if (tid < 256)
            S0g[j*SD + tid] = sm->s0q[0][tid] + sm->s0q[1][tid]
                            + sm->s0q[2][tid] + sm->s0q[3][tid];
        // [C1] pos scalars
        {
            float pdx=0.f, pdy=0.f, pdz=0.f;
#pragma unroll
            for (int r=0;r<2;r++){
                int i = wrp + 16*r;
                float part = 0.f;
#pragma unroll
                for (int m=0;m<8;m++)
                    part += sm->hdn[i][lane+32*m] * sm->w2p[lane+32*m];
#pragma unroll
                for (int off=16; off>0; off>>=1)
                    part += __shfl_xor_sync(0xffffffffu, part, off);
                if (lane==0){
                    float t = part + b2p;
                    pdx += sm->rnb[i][0]*t;
                    pdy += sm->rnb[i][1]*t;
                    pdz += sm->rnb[i][2]*t;
                }
            }
            if (lane==0){ sm->pdpart[wrp][0]=pdx; sm->pdpart[wrp][1]=pdy; sm->pdpart[wrp][2]=pdz; }
        }
        __syncthreads();
    } // j

    if (tid<3){
        float sum=0.f;
#pragma unroll
        for (int w=0;w<16;w++) sum += sm->pdpart[w][tid];
        sm->npos[31][tid] += sum;
    }
    // s += (S0 @ W2s)/31 + b2s
    {
        float acc[HROWS];
#pragma unroll
        for (int r=0;r<HROWS;r++) acc[r]=0.f;
        for (int kg=0; kg<64; kg++){
            float w0=W2[(4*kg+0)*MSG_OUT+c], w1=W2[(4*kg+1)*MSG_OUT+c];
            float w2v=W2[(4*kg+2)*MSG_OUT+c], w3=W2[(4*kg+3)*MSG_OUT+c];
#pragma unroll
            for (int r=0;r<HROWS;r++){
                const float4 v = __ldg((const float4*)&S0g[(r0+r)*SD + 4*kg]);
                acc[r] += v.x*w0 + v.y*w1 + v.z*w2v + v.w*w3;
            }
        }
        float b2s = b2[c];
#pragma unroll
        for (int r=0;r<HROWS;r++)
            sg[(r0+r)*SD + c] += acc[r]*(1.f/31.f) + b2s;
    }
    __syncthreads();
    if (tid<96){
        int i = tid/3, cc = tid%3;
        g_pos[mol*96 + tid] = sm->pos[i][cc] + sm->npos[i][cc]*(1.f/31.f);
    }
}

// ---------------- K2: batched e-update GEMM ----------------
__global__ void __launch_bounds__(256) k2_kernel(const float* __restrict__ gb2, int l)
{
    __shared__ float ws[8192];      // W2e [c4][k][4]
    const int tid = threadIdx.x;
    const int lane = tid & 31;
    const int wrp = tid >> 5;       // 0..7
    {
        const float4* src = (const float4*)(g_w2t + (size_t)l*8192);
        float4* dst = (float4*)ws;
        for (int idx = tid; idx < 2048; idx += 256) dst[idx] = src[idx];
    }
    __syncthreads();
    const float bk = __ldg(&gb2[l*MSG_OUT + 321 + lane]);
    const size_t base = (size_t)blockIdx.x*256 + wrp*32;
#pragma unroll 1
    for (int b8=0; b8<4; b8++){
        size_t e0 = base + b8*8;
        float acc[8];
#pragma unroll
        for (int r=0;r<8;r++) acc[r] = g_e[(e0+r)*ED + lane] + bk;
#pragma unroll 4
        for (int c4=0;c4<64;c4++){
            float4 w4 = *(const float4*)&ws[c4*128 + lane*4];
#pragma unroll
            for (int r=0;r<8;r++){
                const float4 h = __ldg((const float4*)&g_hdn[(e0+r)*SD + 4*c4]);
                acc[r] += h.x*w4.x + h.y*w4.y + h.z*w4.z + h.w*w4.w;
            }
        }
#pragma unroll
        for (int r=0;r<8;r++) g_e[(e0+r)*ED + lane] = acc[r];
    }
}

// ---------------- K3: output heads ----------------
struct SM3 {
    float buf[NPER][SD];    // 32KB multi-use
    float bh [16][128];     // 8KB
    float ebuf[16][ED];     // 2KB
    float pos[NPER][3];
    float dbuf[16];
};

__global__ void __launch_bounds__(NT,2) k3_kernel(
    const float* __restrict__ Wh1, const float* __restrict__ bh1,
    const float* __restrict__ Wh2, const float* __restrict__ bh2,
    const float* __restrict__ We1, const float* __restrict__ be1,
    const float* __restrict__ We2, const float* __restrict__ be2,
    float* __restrict__ outA, float* __restrict__ outB, float* __restrict__ outP)
{
    extern __shared__ float smraw[];
    SM3* sm = (SM3*)smraw;
    const int tid  = threadIdx.x;
    const int lane = tid & 31;
    const int wrp  = tid >> 5;
    const int mol  = blockIdx.x;
    const int nodeBase = mol * NPER;
    const size_t ebase = (size_t)mol * EPM;
    const int c  = tid & 255;
    const int r0 = (tid >> 8) * HROWS;
    const float* sg = g_s + (size_t)mol*NPER*SD;

    if (tid < 96) sm->pos[tid/3][tid%3] = g_pos[mol*96 + tid];

    // atoms = silu(s@Wh1+bh1)@Wh2+bh2
    {
        float acc[HROWS];
#pragma unroll
        for (int r=0;r<HROWS;r++) acc[r]=0.f;
        for (int kg=0; kg<64; kg++){
            float w0=Wh1[(4*kg+0)*SD+c], w1=Wh1[(4*kg+1)*SD+c];
            float w2v=Wh1[(4*kg+2)*SD+c], w3=Wh1[(4*kg+3)*SD+c];
#pragma unroll
            for (int r=0;r<HROWS;r++){
                const float4 v = __ldg((const float4*)&sg[(r0+r)*SD + 4*kg]);
                acc[r] += v.x*w0 + v.y*w1 + v.z*w2v + v.w*w3;
            }
        }
        float bb = bh1[c];
#pragma unroll
        for (int r=0;r<HROWS;r++) sm->buf[r0+r][c] = silu_f(acc[r]+bb);
    }
    __syncthreads();
    for (int o = tid; o < NPER*16; o += NT){
        int i = o>>4, cc = o&15;
        float a = bh2[cc];
        for (int k=0;k<SD;k++) a += sm->buf[i][k]*Wh2[k*16+cc];
        outA[(nodeBase+i)*16+cc] = a;
    }
    if (tid < 96){
        int i = tid/3, cc = tid%3;
        outP[(nodeBase+i)*3+cc] = sm->pos[i][cc];
    }
    __syncthreads();

    // bonds
    float* bP = &sm->buf[0][0];          // 32 x 128
    {
        const int c128 = tid & 127;
        const int grp  = tid >> 7;
        float acc[8];
#pragma unroll
        for (int r=0;r<8;r++) acc[r]=0.f;
        for (int kg=0; kg<64; kg++){
            float w0=We1[(4*kg+0)*128+c128], w1=We1[(4*kg+1)*128+c128];
            float w2v=We1[(4*kg+2)*128+c128], w3=We1[(4*kg+3)*128+c128];
#pragma unroll
            for (int r=0;r<8;r++){
                const float4 v = __ldg((const float4*)&sg[(grp*8+r)*SD + 4*kg]);
                acc[r] += v.x*w0 + v.y*w1 + v.z*w2v + v.w*w3;
            }
        }
#pragma unroll
        for (int r=0;r<8;r++) bP[(grp*8+r)*128 + c128] = acc[r];
    }
    float* We1e_s = &sm->buf[16][0];     // 32 x 128
    for (int idx = tid; idx < 32*128; idx += NT)
        We1e_s[idx] = We1[(256 + (idx>>7))*128 + (idx&127)];
    __syncthreads();

    {
        const int c128 = tid & 127;
        const int grp  = tid >> 7;
        const float w288 = We1[288*128 + c128];
        const float bbe  = be1[c128];
        for (int pblk=0; pblk<62; pblk++){
            for (int idx = tid; idx < 16*ED; idx += NT){
                int q = idx>>5, k = idx&31;
                int eL = pblk*16 + q;
                sm->ebuf[q][k] = g_e[(ebase+eL)*ED + k];
            }
            if (tid < 16){
                int eL = pblk*16 + tid;
                int i = eL/31, jj = eL - i*31; int j = jj + (jj>=i);
                float rx=sm->pos[j][0]-sm->pos[i][0];
                float ry=sm->pos[j][1]-sm->pos[i][1];
                float rz=sm->pos[j][2]-sm->pos[i][2];
                sm->dbuf[tid] = sqrtf(fmaxf(rx*rx+ry*ry+rz*rz, 1e-6f));
            }
            __syncthreads();
#pragma unroll
            for (int qq=0; qq<4; qq++){
                int q = grp*4 + qq;
                int eL = pblk*16 + q;
                int i = eL/31, jj = eL - i*31; int j = jj + (jj>=i);
                float a = bbe + bP[i*128+c128] + bP[j*128+c128] + sm->dbuf[q]*w288;
#pragma unroll
                for (int kg=0; kg<8; kg++){
                    float4 e4 = ((const float4*)&sm->ebuf[q][0])[kg];
                    a += e4.x*We1e_s[(4*kg+0)*128+c128] + e4.y*We1e_s[(4*kg+1)*128+c128]
                       + e4.z*We1e_s[(4*kg+2)*128+c128] + e4.w*We1e_s[(4*kg+3)*128+c128];
                }
                sm->bh[q][c128] = silu_f(a);
            }
            __syncthreads();
            {
                int qq = wrp;
                int eL = pblk*16 + qq;
#pragma unroll
                for (int b=0;b<5;b++){
                    float part = 0.f;
#pragma unroll
                    for (int m=0;m<4;m++){
                        int cc = lane + 32*m;
                        part += sm->bh[qq][cc] * We2[cc*5+b];
                    }
#pragma unroll
                    for (int off=16; off>0; off>>=1)
                        part += __shfl_xor_sync(0xffffffffu, part, off);
                    if (lane==0) outB[(ebase+eL)*5+b] = part + be2[b];
                }
            }
            __syncthreads();
        }
    }
}

extern "C" void kernel_launch(void* const* d_in, const int* in_sizes, int n_in,
                              void* d_out, int out_size)
{
    const float* x    = (const float*)d_in[0];
    const float* z    = (const float*)d_in[1];
    const float* rot  = (const float*)d_in[2];
    const float* eattr= (const float*)d_in[4];
    const float* Wam  = (const float*)d_in[6];
    const float* bam  = (const float*)d_in[7];
    const float* Wbm  = (const float*)d_in[8];
    const float* bbm  = (const float*)d_in[9];
    const float* gW1  = (const float*)d_in[10];
    const float* gb1  = (const float*)d_in[11];
    const float* gW2  = (const float*)d_in[12];
    const float* gb2  = (const float*)d_in[13];
    const float* Wh1  = (const float*)d_in[14];
    const float* bh1  = (const float*)d_in[15];
    const float* Wh2  = (const float*)d_in[16];
    const float* bh2  = (const float*)d_in[17];
    const float* We1  = (const float*)d_in[18];
    const float* be1  = (const float*)d_in[19];
    const float* We2  = (const float*)d_in[20];
    const float* be2  = (const float*)d_in[21];

    float* out  = (float*)d_out;
    float* outA = out;
    float* outB = out + (size_t)NNODE*16;
    float* outP = out + (size_t)NNODE*16 + (size_t)ETOT*5;

    prep_kernel<<<160, 256>>>(gW2);
    k0_kernel<<<NMOL, NT>>>(x, z, rot, eattr, Wam, bam, Wbm, bbm);

    const size_t shm1 = sizeof(SM1);
    cudaFuncSetAttribute(k1_kernel, cudaFuncAttributeMaxDynamicSharedMemorySize, (int)shm1);
    const size_t shm3 = sizeof(SM3);
    cudaFuncSetAttribute(k3_kernel, cudaFuncAttributeMaxDynamicSharedMemorySize, (int)shm3);

    for (int l=0; l<5; l++){
        k1_kernel<<<NMOL, NT, shm1>>>(gW1, gb1, gW2, gb2, l);
        k2_kernel<<<ETOT/256, 256>>>(gb2, l);
    }
    k3_kernel<<<NMOL, NT, shm3>>>(Wh1, bh1, Wh2, bh2, We1, be1, We2, be2,
                                  outA, outB, outP);
}

// round 11
// speedup vs baseline: 1.2857x; 1.2857x over previous
#include <cuda_runtime.h>
#include <math.h>

#define NMOL 256
#define NPER 32
#define NNODE 8192
#define EPM 992
#define ETOT (NMOL*EPM)
#define SD 256
#define ED 32
#define MSG_IN 546
#define MSG_OUT 353
#define NT 512
#define HROWS 16

typedef unsigned long long u64;

// global scratch (sanctioned __device__ arrays)
__device__ float g_e[(size_t)ETOT*ED];                  // edge features (32.5MB, L2)
__device__ __align__(16) float g_w2t [5*64*32*4];       // W2e transposed [l][c4][k][4]
__device__ __align__(16) float g_w1tA[5*8*128*4];       // W1c k-grouped, even cols
__device__ __align__(16) float g_w1tB[5*8*128*4];       // W1c k-grouped, odd cols
__device__ __align__(16) float g_Q [(size_t)NMOL*NPER*SD];
__device__ __align__(16) float g_S0[(size_t)NMOL*NPER*SD];
__device__ __align__(16) float g_s [(size_t)NMOL*NPER*SD];

struct SM {
    float P   [NPER][SD];      // 32KB
    float hdn [2][NPER][SD];   // 64KB (j0/j1)
    float esm [2][NPER][ED];   // 8KB non-dup e rows for j0/j1
    float w2p [SD];            // 1KB
    float pos [NPER][3];
    float npos[NPER][3];
    float dbuf[2][NPER];
    float abuf[2][NPER];
    float rnb [2][NPER][3];
    float pdpart[2][16][3];
};

__device__ __forceinline__ float silu_f(float v){
    return v * (1.0f / (1.0f + __expf(-v)));
}
__device__ __forceinline__ void unpack2(u64 v, float& x, float& y){
    asm("mov.b64 {%0, %1}, %2;" : "=f"(x), "=f"(y) : "l"(v));
}
__device__ __forceinline__ u64 fma2(u64 a, u64 b, u64 c){
    u64 d; asm("fma.rn.f32x2 %0, %1, %2, %3;" : "=l"(d) : "l"(a), "l"(b), "l"(c)); return d;
}

// prep: weight permutations
__global__ void prep_kernel(const float* __restrict__ gW2, const float* __restrict__ gW1){
    int idx = blockIdx.x*256 + threadIdx.x;
    if (idx < 5*8192){
        int l = idx >> 13; int rem = idx & 8191;
        int c4 = rem >> 7; int rem2 = rem & 127;
        int k = rem2 >> 2; int cc = rem2 & 3;
        g_w2t[idx] = gW2[((size_t)l*256 + 4*c4 + cc)*MSG_OUT + 321 + k];
        return;
    }
    idx -= 5*8192;
    if (idx < 2*5*4096){
        int half = idx / (5*4096);
        int r = idx % (5*4096);
        int l = r >> 12; int q = r & 4095;
        int g = q >> 9; int pp = (q >> 2) & 127; int kk = q & 3;
        float v = gW1[((size_t)l*MSG_IN + 512 + 4*g + kk)*SD + 2*pp + half];
        if (half == 0) g_w1tA[l*4096 + q] = v;
        else           g_w1tB[l*4096 + q] = v;
    }
}

__global__ void __launch_bounds__(NT,2) dec_kernel(
    const float* __restrict__ x,   const float* __restrict__ z,
    const float* __restrict__ rot, const float* __restrict__ eattr,
    const float* __restrict__ Wam, const float* __restrict__ bam,
    const float* __restrict__ Wbm, const float* __restrict__ bbm,
    const float* __restrict__ gW1, const float* __restrict__ gb1,
    const float* __restrict__ gW2, const float* __restrict__ gb2,
    const float* __restrict__ Wh1, const float* __restrict__ bh1,
    const float* __restrict__ Wh2, const float* __restrict__ bh2,
    const float* __restrict__ We1, const float* __restrict__ be1,
    const float* __restrict__ We2, const float* __restrict__ be2,
    float* __restrict__ outA, float* __restrict__ outB, float* __restrict__ outP)
{
    extern __shared__ float smraw[];
    SM* sm = (SM*)smraw;
    const int tid  = threadIdx.x;
    const int lane = tid & 31;
    const int wrp  = tid >> 5;
    const int mol  = blockIdx.x;
    const int nodeBase = mol * NPER;
    const size_t ebase = (size_t)mol * EPM;
    const int c  = tid & 255;
    const int r0 = (tid >> 8) * HROWS;
    const int p  = tid & 127;         // col-pair (2p,2p+1) in [B]
    const int rq = (tid >> 7) * 8;    // row quarter start in [B]
    float* Qg  = g_Q  + (size_t)mol*NPER*SD;
    float* S0g = g_S0 + (size_t)mol*NPER*SD;
    float* sg  = g_s  + (size_t)mol*NPER*SD;

    // ---------------- Embed ----------------
    {
        float* xz = &sm->hdn[0][0][0];
        for (int idx = tid; idx < NPER*80; idx += NT){
            int i = idx / 80, k = idx % 80;
            xz[idx] = (k < 16) ? x[(nodeBase+i)*16 + k] : z[(nodeBase+i)*64 + (k-16)];
        }
        __syncthreads();
        float acc[HROWS];
#pragma unroll
        for (int r=0;r<HROWS;r++) acc[r]=0.f;
        for (int kg=0; kg<20; kg++){
            float w0=Wam[(4*kg+0)*259+c], w1=Wam[(4*kg+1)*259+c];
            float w2v=Wam[(4*kg+2)*259+c], w3=Wam[(4*kg+3)*259+c];
#pragma unroll
            for (int r=0;r<HROWS;r++){
                float4 v = ((const float4*)xz)[(r0+r)*20+kg];
                acc[r] += v.x*w0 + v.y*w1 + v.z*w2v + v.w*w3;
            }
        }
        float b = bam[c];
#pragma unroll
        for (int r=0;r<HROWS;r++) sg[(r0+r)*SD + c] = acc[r] + b;
        if (tid < 96){
            int i = tid/3, cc = tid%3;
            float a = bam[256+cc];
            for (int k=0;k<80;k++) a += xz[i*80+k]*Wam[k*259+256+cc];
            sm->npos[i][cc] = a;
        }
        __syncthreads();
        if (tid < 96){
            int i = tid/3, cc = tid%3;
            float pv = 0.f;
#pragma unroll
            for (int q=0;q<3;q++) pv += rot[mol*9 + cc*3 + q]*sm->npos[i][q];
            sm->pos[i][cc] = pv;
        }
    }

    // ---------------- e init ----------------
    for (int idx = tid; idx < EPM*ED; idx += NT){
        int eL = idx >> 5, k = idx & 31;
        const float* ea = &eattr[(ebase+eL)*5];
        float a = bbm[k];
#pragma unroll
        for (int q=0;q<5;q++) a += ea[q]*Wbm[q*ED+k];
        g_e[(ebase+eL)*ED + k] = a;
    }
    __syncthreads();

    // ---------------- 5 layers ----------------
    for (int l=0; l<5; l++){
        const float* W1 = gW1 + (size_t)l*MSG_IN*SD;
        const float* b1 = gb1 + l*SD;
        const float* W2 = gW2 + (size_t)l*SD*MSG_OUT;
        const float* b2 = gb2 + l*MSG_OUT;
        const float* w1A = g_w1tA + l*4096;
        const float* w1B = g_w1tB + l*4096;

        if (tid < 256) sm->w2p[tid] = W2[tid*MSG_OUT + 320];
        if (tid < 96) sm->npos[tid/3][tid%3] = 0.f;

        // P = s@W1a -> SMEM
        {
            float acc[HROWS];
#pragma unroll
            for (int r=0;r<HROWS;r++) acc[r]=0.f;
            for (int kg=0; kg<64; kg++){
                float wa0=W1[(4*kg+0)*SD+c], wa1=W1[(4*kg+1)*SD+c];
                float wa2=W1[(4*kg+2)*SD+c], wa3=W1[(4*kg+3)*SD+c];
#pragma unroll
                for (int r=0;r<HROWS;r++){
                    const float4 v = __ldg((const float4*)&sg[(r0+r)*SD + 4*kg]);
                    acc[r] += v.x*wa0 + v.y*wa1 + v.z*wa2 + v.w*wa3;
                }
            }
#pragma unroll
            for (int r=0;r<HROWS;r++) sm->P[r0+r][c]=acc[r];
        }
        // Q = s@W1b + b1 -> global
        {
            float acc[HROWS];
#pragma unroll
            for (int r=0;r<HROWS;r++) acc[r]=0.f;
            for (int kg=0; kg<64; kg++){
                float wb0=W1[(256+4*kg+0)*SD+c], wb1=W1[(256+4*kg+1)*SD+c];
                float wb2=W1[(256+4*kg+2)*SD+c], wb3=W1[(256+4*kg+3)*SD+c];
#pragma unroll
                for (int r=0;r<HROWS;r++){
                    const float4 v = __ldg((const float4*)&sg[(r0+r)*SD + 4*kg]);
                    acc[r] += v.x*wb0 + v.y*wb1 + v.z*wb2 + v.w*wb3;
                }
            }
            float bb = b1[c];
#pragma unroll
            for (int r=0;r<HROWS;r++) Qg[(r0+r)*SD + c] = acc[r]+bb;
        }
        __syncthreads();

        const float w1dx = __ldg(&W1[544*SD + 2*p]);
        const float w1dy = __ldg(&W1[544*SD + 2*p+1]);
        const float w1ex = __ldg(&W1[545*SD + 2*p]);
        const float w1ey = __ldg(&W1[545*SD + 2*p+1]);
        const float b2p  = __ldg(&b2[320]);
        const float b2k  = __ldg(&b2[321+lane]);
        const float* wt  = g_w2t + l*8192 + lane*4;

        for (int jp=0; jp<16; jp++){
            const int j0 = 2*jp;

            // ---- [A]: fold prev pdparts; stage e rows (non-dup) + geometry ----
            if (jp>0 && tid<6){
                int sel = tid/3, cc = tid - sel*3;
                float sum=0.f;
#pragma unroll
                for (int w=0;w<16;w++) sum += sm->pdpart[sel][w][cc];
                sm->npos[j0-2+sel][cc] += sum;
            }
            for (int idx = tid; idx < 2*NPER*ED; idx += NT){
                int jb = idx >> 10; int rem = idx & 1023;
                int i = rem>>5, k = rem&31;
                int j = j0 + jb;
                float v = 0.f;
                if (i != j) v = g_e[(ebase + i*31 + j - (j>i))*ED + k];
                sm->esm[jb][i][k] = v;
            }
            if (tid < 64){
                int jb = tid>>5, i = tid&31, j = j0+jb;
                float pix=sm->pos[i][0], piy=sm->pos[i][1], piz=sm->pos[i][2];
                float pjx=sm->pos[j][0], pjy=sm->pos[j][1], pjz=sm->pos[j][2];
                float rx=pjx-pix, ry=pjy-piy, rz=pjz-piz;
                float d = sqrtf(fmaxf(rx*rx+ry*ry+rz*rz, 1e-6f));
                float inv = 1.f/(1.f+d);
                sm->dbuf[jb][i]=d; sm->abuf[jb][i]=pix*pjx+piy*pjy+piz*pjz;
                if (i==j){rx=0;ry=0;rz=0;}
                sm->rnb[jb][i][0]=rx*inv; sm->rnb[jb][i][1]=ry*inv; sm->rnb[jb][i][2]=rz*inv;
            }
            __syncthreads();

            // ---- [B]: hdn for j0 then j1 (one phase, regs reused) ----
#pragma unroll 1
            for (int jb=0; jb<2; jb++){
                const int j = j0 + jb;
                u64 acc0[8], acc1[8];
#pragma unroll
                for (int r=0;r<8;r++){ acc0[r]=0ULL; acc1[r]=0ULL; }
#pragma unroll
                for (int g=0;g<8;g++){
                    const ulonglong2 WA = __ldg((const ulonglong2*)&w1A[(g*128+p)*4]);
                    const ulonglong2 WB = __ldg((const ulonglong2*)&w1B[(g*128+p)*4]);
#pragma unroll
                    for (int r=0;r<8;r++){
                        const ulonglong2 E = *(const ulonglong2*)&sm->esm[jb][rq+r][4*g];
                        acc0[r]=fma2(E.x,WA.x,acc0[r]); acc0[r]=fma2(E.y,WA.y,acc0[r]);
                        acc1[r]=fma2(E.x,WB.x,acc1[r]); acc1[r]=fma2(E.y,WB.y,acc1[r]);
                    }
                }
                const u64 qv = __ldg((const u64*)&Qg[j*SD + 2*p]);
                float qx,qy; unpack2(qv,qx,qy);
#pragma unroll
                for (int r=0;r<8;r++){
                    int i = rq+r;
                    float d = sm->dbuf[jb][i], a = sm->abuf[jb][i];
                    const u64 pv = *(const u64*)&sm->P[i][2*p];
                    float px,py; unpack2(pv,px,py);
                    float a0x,a0y,a1x,a1y;
                    unpack2(acc0[r],a0x,a0y); unpack2(acc1[r],a1x,a1y);
                    float h0 = a0x+a0y + px + qx + d*w1dx + a*w1ex;
                    float h1 = a1x+a1y + py + qy + d*w1dy + a*w1ey;
                    h0 = silu_f(h0); h1 = silu_f(h1);
                    if (i==j){ h0=0.f; h1=0.f; }
                    *(float2*)&sm->hdn[jb][i][2*p] = make_float2(h0,h1);
                }
            }
            __syncthreads();

            // ---- [C]: e-update (both js), pos scalars (both js), S0 (both js) ----
            {
                // [C2]: rows {wrp, wrp+16} x {j0,j1}, weights loaded once
                const int i0 = wrp, i1 = wrp + 16;
                u64 a00=0ULL, a01=0ULL, a10=0ULL, a11=0ULL;
#pragma unroll 8
                for (int c4=0;c4<64;c4++){
                    const ulonglong2 ww = *(const ulonglong2*)&wt[c4*128];
                    const ulonglong2 h00 = *(const ulonglong2*)&sm->hdn[0][i0][4*c4];
                    const ulonglong2 h01 = *(const ulonglong2*)&sm->hdn[0][i1][4*c4];
                    const ulonglong2 h10 = *(const ulonglong2*)&sm->hdn[1][i0][4*c4];
                    const ulonglong2 h11 = *(const ulonglong2*)&sm->hdn[1][i1][4*c4];
                    a00=fma2(h00.x,ww.x,a00); a00=fma2(h00.y,ww.y,a00);
                    a01=fma2(h01.x,ww.x,a01); a01=fma2(h01.y,ww.y,a01);
                    a10=fma2(h10.x,ww.x,a10); a10=fma2(h10.y,ww.y,a10);
                    a11=fma2(h11.x,ww.x,a11); a11=fma2(h11.y,ww.y,a11);
                }
                float v00,w00,v01,w01,v10,w10,v11,w11;
                unpack2(a00,v00,w00); unpack2(a01,v01,w01);
                unpack2(a10,v10,w10); unpack2(a11,v11,w11);
                if (i0 != j0){
                    int eL = i0*31 + j0 - (j0>i0);
                    g_e[(ebase+eL)*ED + lane] = v00+w00+b2k + sm->esm[0][i0][lane];
                }
                if (i1 != j0){
                    int eL = i1*31 + j0 - (j0>i1);
                    g_e[(ebase+eL)*ED + lane] = v01+w01+b2k + sm->esm[0][i1][lane];
                }
                if (i0 != j0+1){
                    int eL = i0*31 + (j0+1) - ((j0+1)>i0);
                    g_e[(ebase+eL)*ED + lane] = v10+w10+b2k + sm->esm[1][i0][lane];
                }
                if (i1 != j0+1){
                    int eL = i1*31 + (j0+1) - ((j0+1)>i1);
                    g_e[(ebase+eL)*ED + lane] = v11+w11+b2k + sm->esm[1][i1][lane];
                }
            }
            // [C1] pos scalars for both js
#pragma unroll
            for (int jb=0; jb<2; jb++){
                float pdx=0.f, pdy=0.f, pdz=0.f;
#pragma unroll
                for (int r=0;r<2;r++){
                    int i = wrp + 16*r;
                    float part = 0.f;
#pragma unroll
                    for (int m=0;m<8;m++)
                        part += sm->hdn[jb][i][lane+32*m] * sm->w2p[lane+32*m];
#pragma unroll
                    for (int off=16; off>0; off>>=1)
                        part += __shfl_xor_sync(0xffffffffu, part, off);
                    if (lane==0){
                        float t = part + b2p;
                        pdx += sm->rnb[jb][i][0]*t;
                        pdy += sm->rnb[jb][i][1]*t;
                        pdz += sm->rnb[jb][i][2]*t;
                    }
                }
                if (lane==0){
                    sm->pdpart[jb][wrp][0]=pdx;
                    sm->pdpart[jb][wrp][1]=pdy;
                    sm->pdpart[jb][wrp][2]=pdz;
                }
            }
            // [C0] S0 rows j0,j1 via column sums
            {
                int jb = tid >> 8;
                int col = tid & 255;
                float s0=0.f, s1=0.f;
#pragma unroll
                for (int i=0;i<32;i+=2){
                    s0 += sm->hdn[jb][i][col];
                    s1 += sm->hdn[jb][i+1][col];
                }
                S0g[(j0+jb)*SD + col] = s0 + s1;
            }
            __syncthreads();
        } // jp

        if (tid<6){
            int sel = tid/3, cc = tid - sel*3;
            float sum=0.f;
#pragma unroll
            for (int w=0;w<16;w++) sum += sm->pdpart[sel][w][cc];
            sm->npos[30+sel][cc] += sum;
        }
        // s += (S0 @ W2s)/31 + b2s
        {
            float acc[HROWS];
#pragma unroll
            for (int r=0;r<HROWS;r++) acc[r]=0.f;
            for (int kg=0; kg<64; kg++){
                float w0=W2[(4*kg+0)*MSG_OUT+c], w1=W2[(4*kg+1)*MSG_OUT+c];
                float w2v=W2[(4*kg+2)*MSG_OUT+c], w3=W2[(4*kg+3)*MSG_OUT+c];
#pragma unroll
                for (int r=0;r<HROWS;r++){
                    const float4 v = __ldg((const float4*)&S0g[(r0+r)*SD + 4*kg]);
                    acc[r] += v.x*w0 + v.y*w1 + v.z*w2v + v.w*w3;
                }
            }
            __syncthreads();  // npos folds done; buffers free
            float b2s = b2[c];
#pragma unroll
            for (int r=0;r<HROWS;r++)
                sg[(r0+r)*SD + c] += acc[r]*(1.f/31.f) + b2s;
        }
        if (tid<96){
            int i = tid/3, cc = tid%3;
            sm->pos[i][cc] += sm->npos[i][cc]*(1.f/31.f);
        }
        __syncthreads();
    } // layers

    // ---------------- atoms + pos out ----------------
    {
        float acc[HROWS];
#pragma unroll
        for (int r=0;r<HROWS;r++) acc[r]=0.f;
        for (int kg=0; kg<64; kg++){
            float w0=Wh1[(4*kg+0)*SD+c], w1=Wh1[(4*kg+1)*SD+c];
            float w2v=Wh1[(4*kg+2)*SD+c], w3=Wh1[(4*kg+3)*SD+c];
#pragma unroll
            for (int r=0;r<HROWS;r++){
                const float4 v = __ldg((const float4*)&sg[(r0+r)*SD + 4*kg]);
                acc[r] += v.x*w0 + v.y*w1 + v.z*w2v + v.w*w3;
            }
        }
        float bb = bh1[c];
#pragma unroll
        for (int r=0;r<HROWS;r++) sm->P[r0+r][c] = silu_f(acc[r]+bb);
    }
    __syncthreads();
    for (int o = tid; o < NPER*16; o += NT){
        int i = o>>4, cc = o&15;
        float a = bh2[cc];
        for (int k=0;k<SD;k++) a += sm->P[i][k]*Wh2[k*16+cc];
        outA[(nodeBase+i)*16+cc] = a;
    }
    if (tid < 96){
        int i = tid/3, cc = tid%3;
        outP[(nodeBase+i)*3+cc] = sm->pos[i][cc];
    }
    __syncthreads();

    // ---------------- bonds ----------------
    float* hdnf = &sm->hdn[0][0][0];
    float* bP = hdnf;                    // 32 x 128
    {
        const int c128 = tid & 127;
        const int grp  = tid >> 7;
        float acc[8];
#pragma unroll
        for (int r=0;r<8;r++) acc[r]=0.f;
        for (int kg=0; kg<64; kg++){
            float w0=We1[(4*kg+0)*128+c128], w1=We1[(4*kg+1)*128+c128];
            float w2v=We1[(4*kg+2)*128+c128], w3=We1[(4*kg+3)*128+c128];
#pragma unroll
            for (int r=0;r<8;r++){
                const float4 v = __ldg((const float4*)&sg[(grp*8+r)*SD + 4*kg]);
                acc[r] += v.x*w0 + v.y*w1 + v.z*w2v + v.w*w3;
            }
        }
#pragma unroll
        for (int r=0;r<8;r++) bP[(grp*8+r)*128 + c128] = acc[r];
    }
    float* We1e_s = hdnf + 16*SD;        // 32 x 128
    for (int idx = tid; idx < 32*128; idx += NT)
        We1e_s[idx] = We1[(256 + (idx>>7))*128 + (idx&127)];
    __syncthreads();

    float* bh = &sm->hdn[1][0][0];       // 16 x 128
    float* ebuf = &sm->esm[0][0][0];     // 16 x 32
    {
        const int c128 = tid & 127;
        const int grp  = tid >> 7;
        const float w288 = We1[288*128 + c128];
        const float bbe  = be1[c128];
        for (int pblk=0; pblk<62; pblk++){
            for (int idx = tid; idx < 16*ED; idx += NT){
                int q = idx>>5, k = idx&31;
                int eL = pblk*16 + q;
                ebuf[q*32+k] = g_e[(ebase+eL)*ED + k];
            }
            if (tid < 16){
                int eL = pblk*16 + tid;
                int i = eL/31, jj = eL - i*31; int j = jj + (jj>=i);
                float rx=sm->pos[j][0]-sm->pos[i][0];
                float ry=sm->pos[j][1]-sm->pos[i][1];
                float rz=sm->pos[j][2]-sm->pos[i][2];
                sm->dbuf[0][tid] = sqrtf(fmaxf(rx*rx+ry*ry+rz*rz, 1e-6f));
            }
            __syncthreads();
#pragma unroll
            for (int qq=0; qq<4; qq++){
                int q = grp*4 + qq;
                int eL = pblk*16 + q;
                int i = eL/31, jj = eL - i*31; int j = jj + (jj>=i);
                float a = bbe + bP[i*128+c128] + bP[j*128+c128] + sm->dbuf[0][q]*w288;
#pragma unroll
                for (int kg=0; kg<8; kg++){
                    float4 e4 = ((const float4*)&ebuf[q*32])[kg];
                    a += e4.x*We1e_s[(4*kg+0)*128+c128] + e4.y*We1e_s[(4*kg+1)*128+c128]
                       + e4.z*We1e_s[(4*kg+2)*128+c128] + e4.w*We1e_s[(4*kg+3)*128+c128];
                }
                bh[q*128+c128] = silu_f(a);
            }
            __syncthreads();
            {
                int qq = wrp;
                int eL = pblk*16 + qq;
#pragma unroll
                for (int b=0;b<5;b++){
                    float part = 0.f;
#pragma unroll
                    for (int m=0;m<4;m++){
                        int cc = lane + 32*m;
                        part += bh[qq*128+cc] * We2[cc*5+b];
                    }
#pragma unroll
                    for (int off=16; off>0; off>>=1)
                        part += __shfl_xor_sync(0xffffffffu, part, off);
                    if (lane==0) outB[(ebase+eL)*5+b] = part + be2[b];
                }
            }
            __syncthreads();
        }
    }
}

extern "C" void kernel_launch(void* const* d_in, const int* in_sizes, int n_in,
                              void* d_out, int out_size)
{
    const float* x    = (const float*)d_in[0];
    const float* z    = (const float*)d_in[1];
    const float* rot  = (const float*)d_in[2];
    const float* eattr= (const float*)d_in[4];
    const float* Wam  = (const float*)d_in[6];
    const float* bam  = (const float*)d_in[7];
    const float* Wbm  = (const float*)d_in[8];
    const float* bbm  = (const float*)d_in[9];
    const float* gW1  = (const float*)d_in[10];
    const float* gb1  = (const float*)d_in[11];
    const float* gW2  = (const float*)d_in[12];
    const float* gb2  = (const float*)d_in[13];
    const float* Wh1  = (const float*)d_in[14];
    const float* bh1  = (const float*)d_in[15];
    const float* Wh2  = (const float*)d_in[16];
    const float* bh2  = (const float*)d_in[17];
    const float* We1  = (const float*)d_in[18];
    const float* be1  = (const float*)d_in[19];
    const float* We2  = (const float*)d_in[20];
    const float* be2  = (const float*)d_in[21];

    float* out  = (float*)d_out;
    float* outA = out;
    float* outB = out + (size_t)NNODE*16;
    float* outP = out + (size_t)NNODE*16 + (size_t)ETOT*5;

    prep_kernel<<<320, 256>>>(gW2, gW1);

    const size_t shmem = sizeof(SM);
    cudaFuncSetAttribute(dec_kernel, cudaFuncAttributeMaxDynamicSharedMemorySize, (int)shmem);
    dec_kernel<<<NMOL, NT, shmem>>>(x,z,rot,eattr,Wam,bam,Wbm,bbm,
                                    gW1,gb1,gW2,gb2,Wh1,bh1,Wh2,bh2,
                                    We1,be1,We2,be2,outA,outB,outP);
}

// round 12
// speedup vs baseline: 1.3395x; 1.0419x over previous
#include <cuda_runtime.h>
#include <math.h>

#define NMOL 256
#define NPER 32
#define NNODE 8192
#define EPM 992
#define ETOT (NMOL*EPM)
#define SD 256
#define ED 32
#define MSG_IN 546
#define MSG_OUT 353
#define NT 512
#define HROWS 16

typedef unsigned long long u64;

// global scratch (sanctioned __device__ arrays)
__device__ float g_e[(size_t)ETOT*ED];                  // edge features (32.5MB, L2)
__device__ __align__(16) float g_w2t [5*64*32*4];       // W2e transposed [l][c4][k][4]
__device__ __align__(16) float g_w1tA[5*8*128*4];       // W1c k-grouped, even cols
__device__ __align__(16) float g_w1tB[5*8*128*4];       // W1c k-grouped, odd cols
__device__ __align__(16) float g_Q [(size_t)NMOL*NPER*SD];
__device__ __align__(16) float g_S0[(size_t)NMOL*NPER*SD];
__device__ __align__(16) float g_s [(size_t)NMOL*NPER*SD];

struct SM {
    float P   [NPER][SD];      // 32KB
    float hdn [2][NPER][SD];   // 64KB (j0/j1)
    float esm [2][NPER][ED];   // 8KB non-dup e rows for j0/j1
    float w2p [SD];            // 1KB
    float pos [NPER][3];
    float npos[NPER][3];
    float dbuf[2][NPER];
    float abuf[2][NPER];
    float rnb [2][NPER][3];
    float pdpart[2][16][3];
};

__device__ __forceinline__ float silu_f(float v){
    return v * (1.0f / (1.0f + __expf(-v)));
}
__device__ __forceinline__ void unpack2(u64 v, float& x, float& y){
    asm("mov.b64 {%0, %1}, %2;" : "=f"(x), "=f"(y) : "l"(v));
}
__device__ __forceinline__ u64 fma2(u64 a, u64 b, u64 c){
    u64 d; asm("fma.rn.f32x2 %0, %1, %2, %3;" : "=l"(d) : "l"(a), "l"(b), "l"(c)); return d;
}

// prep: weight permutations
__global__ void prep_kernel(const float* __restrict__ gW2, const float* __restrict__ gW1){
    int idx = blockIdx.x*256 + threadIdx.x;
    if (idx < 5*8192){
        int l = idx >> 13; int rem = idx & 8191;
        int c4 = rem >> 7; int rem2 = rem & 127;
        int k = rem2 >> 2; int cc = rem2 & 3;
        g_w2t[idx] = gW2[((size_t)l*256 + 4*c4 + cc)*MSG_OUT + 321 + k];
        return;
    }
    idx -= 5*8192;
    if (idx < 2*5*4096){
        int half = idx / (5*4096);
        int r = idx % (5*4096);
        int l = r >> 12; int q = r & 4095;
        int g = q >> 9; int pp = (q >> 2) & 127; int kk = q & 3;
        float v = gW1[((size_t)l*MSG_IN + 512 + 4*g + kk)*SD + 2*pp + half];
        if (half == 0) g_w1tA[l*4096 + q] = v;
        else           g_w1tB[l*4096 + q] = v;
    }
}

__global__ void __launch_bounds__(NT,2) dec_kernel(
    const float* __restrict__ x,   const float* __restrict__ z,
    const float* __restrict__ rot, const float* __restrict__ eattr,
    const float* __restrict__ Wam, const float* __restrict__ bam,
    const float* __restrict__ Wbm, const float* __restrict__ bbm,
    const float* __restrict__ gW1, const float* __restrict__ gb1,
    const float* __restrict__ gW2, const float* __restrict__ gb2,
    const float* __restrict__ Wh1, const float* __restrict__ bh1,
    const float* __restrict__ Wh2, const float* __restrict__ bh2,
    const float* __restrict__ We1, const float* __restrict__ be1,
    const float* __restrict__ We2, const float* __restrict__ be2,
    float* __restrict__ outA, float* __restrict__ outB, float* __restrict__ outP)
{
    extern __shared__ float smraw[];
    SM* sm = (SM*)smraw;
    const int tid  = threadIdx.x;
    const int lane = tid & 31;
    const int wrp  = tid >> 5;
    const int mol  = blockIdx.x;
    const int nodeBase = mol * NPER;
    const size_t ebase = (size_t)mol * EPM;
    const int c  = tid & 255;
    const int r0 = (tid >> 8) * HROWS;
    const int p  = tid & 127;         // col-pair (2p,2p+1) in [B]
    const int rq = (tid >> 7) * 8;    // row quarter start in [B]
    float* Qg  = g_Q  + (size_t)mol*NPER*SD;
    float* S0g = g_S0 + (size_t)mol*NPER*SD;
    float* sg  = g_s  + (size_t)mol*NPER*SD;

    // ---------------- Embed ----------------
    {
        float* xz = &sm->hdn[0][0][0];
        for (int idx = tid; idx < NPER*80; idx += NT){
            int i = idx / 80, k = idx % 80;
            xz[idx] = (k < 16) ? x[(nodeBase+i)*16 + k] : z[(nodeBase+i)*64 + (k-16)];
        }
        __syncthreads();
        float acc[HROWS];
#pragma unroll
        for (int r=0;r<HROWS;r++) acc[r]=0.f;
        for (int kg=0; kg<20; kg++){
            float w0=Wam[(4*kg+0)*259+c], w1=Wam[(4*kg+1)*259+c];
            float w2v=Wam[(4*kg+2)*259+c], w3=Wam[(4*kg+3)*259+c];
#pragma unroll
            for (int r=0;r<HROWS;r++){
                float4 v = ((const float4*)xz)[(r0+r)*20+kg];
                acc[r] += v.x*w0 + v.y*w1 + v.z*w2v + v.w*w3;
            }
        }
        float b = bam[c];
#pragma unroll
        for (int r=0;r<HROWS;r++) sg[(r0+r)*SD + c] = acc[r] + b;
        if (tid < 96){
            int i = tid/3, cc = tid%3;
            float a = bam[256+cc];
            for (int k=0;k<80;k++) a += xz[i*80+k]*Wam[k*259+256+cc];
            sm->npos[i][cc] = a;
        }
        __syncthreads();
        if (tid < 96){
            int i = tid/3, cc = tid%3;
            float pv = 0.f;
#pragma unroll
            for (int q=0;q<3;q++) pv += rot[mol*9 + cc*3 + q]*sm->npos[i][q];
            sm->pos[i][cc] = pv;
        }
    }

    // ---------------- e init ----------------
    for (int idx = tid; idx < EPM*ED; idx += NT){
        int eL = idx >> 5, k = idx & 31;
        const float* ea = &eattr[(ebase+eL)*5];
        float a = bbm[k];
#pragma unroll
        for (int q=0;q<5;q++) a += ea[q]*Wbm[q*ED+k];
        g_e[(ebase+eL)*ED + k] = a;
    }
    __syncthreads();

    // ---------------- 5 layers ----------------
    for (int l=0; l<5; l++){
        const float* W1 = gW1 + (size_t)l*MSG_IN*SD;
        const float* b1 = gb1 + l*SD;
        const float* W2 = gW2 + (size_t)l*SD*MSG_OUT;
        const float* b2 = gb2 + l*MSG_OUT;
        const float* w1A = g_w1tA + l*4096;
        const float* w1B = g_w1tB + l*4096;

        if (tid < 256) sm->w2p[tid] = W2[tid*MSG_OUT + 320];
        if (tid < 96) sm->npos[tid/3][tid%3] = 0.f;

        // P = s@W1a -> SMEM
        {
            float acc[HROWS];
#pragma unroll
            for (int r=0;r<HROWS;r++) acc[r]=0.f;
            for (int kg=0; kg<64; kg++){
                float wa0=W1[(4*kg+0)*SD+c], wa1=W1[(4*kg+1)*SD+c];
                float wa2=W1[(4*kg+2)*SD+c], wa3=W1[(4*kg+3)*SD+c];
#pragma unroll
                for (int r=0;r<HROWS;r++){
                    const float4 v = __ldg((const float4*)&sg[(r0+r)*SD + 4*kg]);
                    acc[r] += v.x*wa0 + v.y*wa1 + v.z*wa2 + v.w*wa3;
                }
            }
#pragma unroll
            for (int r=0;r<HROWS;r++) sm->P[r0+r][c]=acc[r];
        }
        // Q = s@W1b + b1 -> global
        {
            float acc[HROWS];
#pragma unroll
            for (int r=0;r<HROWS;r++) acc[r]=0.f;
            for (int kg=0; kg<64; kg++){
                float wb0=W1[(256+4*kg+0)*SD+c], wb1=W1[(256+4*kg+1)*SD+c];
                float wb2=W1[(256+4*kg+2)*SD+c], wb3=W1[(256+4*kg+3)*SD+c];
#pragma unroll
                for (int r=0;r<HROWS;r++){
                    const float4 v = __ldg((const float4*)&sg[(r0+r)*SD + 4*kg]);
                    acc[r] += v.x*wb0 + v.y*wb1 + v.z*wb2 + v.w*wb3;
                }
            }
            float bb = b1[c];
#pragma unroll
            for (int r=0;r<HROWS;r++) Qg[(r0+r)*SD + c] = acc[r]+bb;
        }
        __syncthreads();

        const float w1dx = __ldg(&W1[544*SD + 2*p]);
        const float w1dy = __ldg(&W1[544*SD + 2*p+1]);
        const float w1ex = __ldg(&W1[545*SD + 2*p]);
        const float w1ey = __ldg(&W1[545*SD + 2*p+1]);
        const float b2p  = __ldg(&b2[320]);
        const float b2k  = __ldg(&b2[321+lane]);

        for (int jp=0; jp<16; jp++){
            const int j0 = 2*jp;

            // ---- [A]: fold prev pdparts; stage e rows (non-dup) + geometry ----
            if (jp>0 && tid<6){
                int sel = tid/3, cc = tid - sel*3;
                float sum=0.f;
#pragma unroll
                for (int w=0;w<16;w++) sum += sm->pdpart[sel][w][cc];
                sm->npos[j0-2+sel][cc] += sum;
            }
            for (int idx = tid; idx < 2*NPER*ED; idx += NT){
                int jb = idx >> 10; int rem = idx & 1023;
                int i = rem>>5, k = rem&31;
                int j = j0 + jb;
                float v = 0.f;
                if (i != j) v = g_e[(ebase + i*31 + j - (j>i))*ED + k];
                sm->esm[jb][i][k] = v;
            }
            if (tid < 64){
                int jb = tid>>5, i = tid&31, j = j0+jb;
                float pix=sm->pos[i][0], piy=sm->pos[i][1], piz=sm->pos[i][2];
                float pjx=sm->pos[j][0], pjy=sm->pos[j][1], pjz=sm->pos[j][2];
                float rx=pjx-pix, ry=pjy-piy, rz=pjz-piz;
                float d = sqrtf(fmaxf(rx*rx+ry*ry+rz*rz, 1e-6f));
                float inv = 1.f/(1.f+d);
                sm->dbuf[jb][i]=d; sm->abuf[jb][i]=pix*pjx+piy*pjy+piz*pjz;
                if (i==j){rx=0;ry=0;rz=0;}
                sm->rnb[jb][i][0]=rx*inv; sm->rnb[jb][i][1]=ry*inv; sm->rnb[jb][i][2]=rz*inv;
            }
            __syncthreads();

            // ---- [B]: hdn for j0 then j1 (one phase, regs reused) ----
#pragma unroll 1
            for (int jb=0; jb<2; jb++){
                const int j = j0 + jb;
                u64 acc0[8], acc1[8];
#pragma unroll
                for (int r=0;r<8;r++){ acc0[r]=0ULL; acc1[r]=0ULL; }
#pragma unroll
                for (int g=0;g<8;g++){
                    const ulonglong2 WA = __ldg((const ulonglong2*)&w1A[(g*128+p)*4]);
                    const ulonglong2 WB = __ldg((const ulonglong2*)&w1B[(g*128+p)*4]);
#pragma unroll
                    for (int r=0;r<8;r++){
                        const ulonglong2 E = *(const ulonglong2*)&sm->esm[jb][rq+r][4*g];
                        acc0[r]=fma2(E.x,WA.x,acc0[r]); acc0[r]=fma2(E.y,WA.y,acc0[r]);
                        acc1[r]=fma2(E.x,WB.x,acc1[r]); acc1[r]=fma2(E.y,WB.y,acc1[r]);
                    }
                }
                const u64 qv = __ldg((const u64*)&Qg[j*SD + 2*p]);
                float qx,qy; unpack2(qv,qx,qy);
#pragma unroll
                for (int r=0;r<8;r++){
                    int i = rq+r;
                    float d = sm->dbuf[jb][i], a = sm->abuf[jb][i];
                    const u64 pv = *(const u64*)&sm->P[i][2*p];
                    float px,py; unpack2(pv,px,py);
                    float a0x,a0y,a1x,a1y;
                    unpack2(acc0[r],a0x,a0y); unpack2(acc1[r],a1x,a1y);
                    float h0 = a0x+a0y + px + qx + d*w1dx + a*w1ex;
                    float h1 = a1x+a1y + py + qy + d*w1dy + a*w1ey;
                    h0 = silu_f(h0); h1 = silu_f(h1);
                    if (i==j){ h0=0.f; h1=0.f; }
                    *(float2*)&sm->hdn[jb][i][2*p] = make_float2(h0,h1);
                }
            }
            __syncthreads();

            // ---- [C]: e-update (quarter-column partial + RED), pos scalars, S0 ----
            {
                // [C2]: warp = (quarter qq of columns) x (group of 16 streams)
                const int qq  = wrp >> 2;        // 0..3 column quarter
                const int sub = wrp & 3;         // 0..3 stream group
                const float* wtq = g_w2t + l*8192 + lane*4;
                u64 acc[16];
#pragma unroll
                for (int m=0;m<16;m++) acc[m]=0ULL;
#pragma unroll 4
                for (int cc4=0; cc4<16; cc4++){
                    const int c4 = qq*16 + cc4;
                    const ulonglong2 ww = *(const ulonglong2*)&wtq[c4*128];
                    const float* hb = &sm->hdn[0][0][4*c4] + (size_t)sub*16*SD;
#pragma unroll
                    for (int m=0;m<16;m++){
                        const ulonglong2 hv = *(const ulonglong2*)(hb + m*SD);
                        acc[m]=fma2(hv.x,ww.x,acc[m]); acc[m]=fma2(hv.y,ww.y,acc[m]);
                    }
                }
#pragma unroll
                for (int m=0;m<16;m++){
                    int st = sub*16 + m;         // 0..63 = jb*32 + i
                    int jb = st >> 5, i = st & 31;
                    int j = j0 + jb;
                    if (i != j){
                        float ax,ay; unpack2(acc[m],ax,ay);
                        float val = ax + ay + (qq==0 ? b2k : 0.f);
                        int eL = i*31 + j - (j>i);
                        atomicAdd(&g_e[(ebase+eL)*ED + lane], val);
                    }
                }
            }
            // [C1] pos scalars for both js
#pragma unroll
            for (int jb=0; jb<2; jb++){
                float pdx=0.f, pdy=0.f, pdz=0.f;
#pragma unroll
                for (int r=0;r<2;r++){
                    int i = wrp + 16*r;
                    float part = 0.f;
#pragma unroll
                    for (int m=0;m<8;m++)
                        part += sm->hdn[jb][i][lane+32*m] * sm->w2p[lane+32*m];
#pragma unroll
                    for (int off=16; off>0; off>>=1)
                        part += __shfl_xor_sync(0xffffffffu, part, off);
                    if (lane==0){
                        float t = part + b2p;
                        pdx += sm->rnb[jb][i][0]*t;
                        pdy += sm->rnb[jb][i][1]*t;
                        pdz += sm->rnb[jb][i][2]*t;
                    }
                }
                if (lane==0){
                    sm->pdpart[jb][wrp][0]=pdx;
                    sm->pdpart[jb][wrp][1]=pdy;
                    sm->pdpart[jb][wrp][2]=pdz;
                }
            }
            // [C0] S0 rows j0,j1 via column sums
            {
                int jb = tid >> 8;
                int col = tid & 255;
                float s0=0.f, s1=0.f;
#pragma unroll
                for (int i=0;i<32;i+=2){
                    s0 += sm->hdn[jb][i][col];
                    s1 += sm->hdn[jb][i+1][col];
                }
                S0g[(j0+jb)*SD + col] = s0 + s1;
            }
            __syncthreads();
        } // jp

        if (tid<6){
            int sel = tid/3, cc = tid - sel*3;
            float sum=0.f;
#pragma unroll
            for (int w=0;w<16;w++) sum += sm->pdpart[sel][w][cc];
            sm->npos[30+sel][cc] += sum;
        }
        // s += (S0 @ W2s)/31 + b2s
        {
            float acc[HROWS];
#pragma unroll
            for (int r=0;r<HROWS;r++) acc[r]=0.f;
            for (int kg=0; kg<64; kg++){
                float w0=W2[(4*kg+0)*MSG_OUT+c], w1=W2[(4*kg+1)*MSG_OUT+c];
                float w2v=W2[(4*kg+2)*MSG_OUT+c], w3=W2[(4*kg+3)*MSG_OUT+c];
#pragma unroll
                for (int r=0;r<HROWS;r++){
                    const float4 v = __ldg((const float4*)&S0g[(r0+r)*SD + 4*kg]);
                    acc[r] += v.x*w0 + v.y*w1 + v.z*w2v + v.w*w3;
                }
            }
            __syncthreads();  // npos folds done; buffers free
            float b2s = b2[c];
#pragma unroll
            for (int r=0;r<HROWS;r++)
                sg[(r0+r)*SD + c] += acc[r]*(1.f/31.f) + b2s;
        }
        if (tid<96){
            int i = tid/3, cc = tid%3;
            sm->pos[i][cc] += sm->npos[i][cc]*(1.f/31.f);
        }
        __syncthreads();
    } // layers

    // ---------------- atoms + pos out ----------------
    {
        float acc[HROWS];
#pragma unroll
        for (int r=0;r<HROWS;r++) acc[r]=0.f;
        for (int kg=0; kg<64; kg++){
            float w0=Wh1[(4*kg+0)*SD+c], w1=Wh1[(4*kg+1)*SD+c];
            float w2v=Wh1[(4*kg+2)*SD+c], w3=Wh1[(4*kg+3)*SD+c];
#pragma unroll
            for (int r=0;r<HROWS;r++){
                const float4 v = __ldg((const float4*)&sg[(r0+r)*SD + 4*kg]);
                acc[r] += v.x*w0 + v.y*w1 + v.z*w2v + v.w*w3;
            }
        }
        float bb = bh1[c];
#pragma unroll
        for (int r=0;r<HROWS;r++) sm->P[r0+r][c] = silu_f(acc[r]+bb);
    }
    __syncthreads();
    for (int o = tid; o < NPER*16; o += NT){
        int i = o>>4, cc = o&15;
        float a = bh2[cc];
        for (int k=0;k<SD;k++) a += sm->P[i][k]*Wh2[k*16+cc];
        outA[(nodeBase+i)*16+cc] = a;
    }
    if (tid < 96){
        int i = tid/3, cc = tid%3;
        outP[(nodeBase+i)*3+cc] = sm->pos[i][cc];
    }
    __syncthreads();

    // ---------------- bonds ----------------
    float* hdnf = &sm->hdn[0][0][0];
    float* bP = hdnf;                    // 32 x 128
    {
        const int c128 = tid & 127;
        const int grp  = tid >> 7;
        float acc[8];
#pragma unroll
        for (int r=0;r<8;r++) acc[r]=0.f;
        for (int kg=0; kg<64; kg++){
            float w0=We1[(4*kg+0)*128+c128], w1=We1[(4*kg+1)*128+c128];
            float w2v=We1[(4*kg+2)*128+c128], w3=We1[(4*kg+3)*128+c128];
#pragma unroll
            for (int r=0;r<8;r++){
                const float4 v = __ldg((const float4*)&sg[(grp*8+r)*SD + 4*kg]);
                acc[r] += v.x*w0 + v.y*w1 + v.z*w2v + v.w*w3;
            }
        }
#pragma unroll
        for (int r=0;r<8;r++) bP[(grp*8+r)*128 + c128] = acc[r];
    }
    float* We1e_s = hdnf + 16*SD;        // 32 x 128
    for (int idx = tid; idx < 32*128; idx += NT)
        We1e_s[idx] = We1[(256 + (idx>>7))*128 + (idx&127)];
    __syncthreads();

    float* bh = &sm->hdn[1][0][0];       // 16 x 128
    float* ebuf = &sm->esm[0][0][0];     // 16 x 32
    {
        const int c128 = tid & 127;
        const int grp  = tid >> 7;
        const float w288 = We1[288*128 + c128];
        const float bbe  = be1[c128];
        for (int pblk=0; pblk<62; pblk++){
            for (int idx = tid; idx < 16*ED; idx += NT){
                int q = idx>>5, k = idx&31;
                int eL = pblk*16 + q;
                ebuf[q*32+k] = g_e[(ebase+eL)*ED + k];
            }
            if (tid < 16){
                int eL = pblk*16 + tid;
                int i = eL/31, jj = eL - i*31; int j = jj + (jj>=i);
                float rx=sm->pos[j][0]-sm->pos[i][0];
                float ry=sm->pos[j][1]-sm->pos[i][1];
                float rz=sm->pos[j][2]-sm->pos[i][2];
                sm->dbuf[0][tid] = sqrtf(fmaxf(rx*rx+ry*ry+rz*rz, 1e-6f));
            }
            __syncthreads();
#pragma unroll
            for (int qq=0; qq<4; qq++){
                int q = grp*4 + qq;
                int eL = pblk*16 + q;
                int i = eL/31, jj = eL - i*31; int j = jj + (jj>=i);
                float a = bbe + bP[i*128+c128] + bP[j*128+c128] + sm->dbuf[0][q]*w288;
#pragma unroll
                for (int kg=0; kg<8; kg++){
                    float4 e4 = ((const float4*)&ebuf[q*32])[kg];
                    a += e4.x*We1e_s[(4*kg+0)*128+c128] + e4.y*We1e_s[(4*kg+1)*128+c128]
                       + e4.z*We1e_s[(4*kg+2)*128+c128] + e4.w*We1e_s[(4*kg+3)*128+c128];
                }
                bh[q*128+c128] = silu_f(a);
            }
            __syncthreads();
            {
                int qq = wrp;
                int eL = pblk*16 + qq;
#pragma unroll
                for (int b=0;b<5;b++){
                    float part = 0.f;
#pragma unroll
                    for (int m=0;m<4;m++){
                        int cc = lane + 32*m;
                        part += bh[qq*128+cc] * We2[cc*5+b];
                    }
#pragma unroll
                    for (int off=16; off>0; off>>=1)
                        part += __shfl_xor_sync(0xffffffffu, part, off);
                    if (lane==0) outB[(ebase+eL)*5+b] = part + be2[b];
                }
            }
            __syncthreads();
        }
    }
}

extern "C" void kernel_launch(void* const* d_in, const int* in_sizes, int n_in,
                              void* d_out, int out_size)
{
    const float* x    = (const float*)d_in[0];
    const float* z    = (const float*)d_in[1];
    const float* rot  = (const float*)d_in[2];
    const float* eattr= (const float*)d_in[4];
    const float* Wam  = (const float*)d_in[6];
    const float* bam  = (const float*)d_in[7];
    const float* Wbm  = (const float*)d_in[8];
    const float* bbm  = (const float*)d_in[9];
    const float* gW1  = (const float*)d_in[10];
    const float* gb1  = (const float*)d_in[11];
    const float* gW2  = (const float*)d_in[12];
    const float* gb2  = (const float*)d_in[13];
    const float* Wh1  = (const float*)d_in[14];
    const float* bh1  = (const float*)d_in[15];
    const float* Wh2  = (const float*)d_in[16];
    const float* bh2  = (const float*)d_in[17];
    const float* We1  = (const float*)d_in[18];
    const float* be1  = (const float*)d_in[19];
    const float* We2  = (const float*)d_in[20];
    const float* be2  = (const float*)d_in[21];

    float* out  = (float*)d_out;
    float* outA = out;
    float* outB = out + (size_t)NNODE*16;
    float* outP = out + (size_t)NNODE*16 + (size_t)ETOT*5;

    prep_kernel<<<320, 256>>>(gW2, gW1);

    const size_t shmem = sizeof(SM);
    cudaFuncSetAttribute(dec_kernel, cudaFuncAttributeMaxDynamicSharedMemorySize, (int)shmem);
    dec_kernel<<<NMOL, NT, shmem>>>(x,z,rot,eattr,Wam,bam,Wbm,bbm,
                                    gW1,gb1,gW2,gb2,Wh1,bh1,Wh2,bh2,
                                    We1,be1,We2,be2,outA,outB,outP);
}